// round 7
// baseline (speedup 1.0000x reference)
#include <cuda_runtime.h>
#include <cuda_fp16.h>
#include <math.h>
#include <stdint.h>

// Problem constants
#define BDIM   32
#define NTRAJ  512
#define LAT    256
#define HID    1024
#define TSTEPS 10
#define NROWS  (NTRAJ + LAT)        // 768
#define MTOT   (BDIM * NROWS)       // 24576

// ---------------- scratch ----------------------------------------------------
__device__ __align__(16) float  g_x   [MTOT * LAT];   // committed state (fp32)
__device__ __align__(16) float  g_ksum[MTOT * LAT];   // weighted k accum (fp32)
__device__ __align__(16) __half g_xin [MTOT * LAT];   // next eval input (fp16)
__device__ __align__(16) __half g_h   [MTOT * HID];   // hidden (fp16)
__device__ __align__(16) __half g_W1T [HID * LAT];    // W1^T [n=1024][k=256]
__device__ __align__(16) __half g_W2T [LAT * HID];    // W2^T [n=256][k=1024]
__device__ float g_mean[BDIM * LAT];
__device__ float g_cov [BDIM * LAT * LAT];

// ---------------- helpers -----------------------------------------------------
__device__ __forceinline__ float tanh_fast(float x) {
    float y;
    asm("tanh.approx.f32 %0, %1;" : "=f"(y) : "f"(x));
    return y;
}

__device__ __forceinline__ void mma_fp16(float* d, const uint32_t* a,
                                         uint32_t b0, uint32_t b1) {
    asm("mma.sync.aligned.m16n8k16.row.col.f32.f16.f16.f32 "
        "{%0,%1,%2,%3},{%4,%5,%6,%7},{%8,%9},{%0,%1,%2,%3};"
        : "+f"(d[0]), "+f"(d[1]), "+f"(d[2]), "+f"(d[3])
        : "r"(a[0]), "r"(a[1]), "r"(a[2]), "r"(a[3]), "r"(b0), "r"(b1));
}

__device__ __forceinline__ void ldsm4(uint32_t* r, uint32_t addr) {
    asm volatile("ldmatrix.sync.aligned.m8n8.x4.shared.b16 {%0,%1,%2,%3}, [%4];"
                 : "=r"(r[0]), "=r"(r[1]), "=r"(r[2]), "=r"(r[3]) : "r"(addr));
}

__device__ __forceinline__ void cp16(uint32_t dst, const void* src) {
    asm volatile("cp.async.cg.shared.global [%0], [%1], 16;"
                 :: "r"(dst), "l"(src));
}
__device__ __forceinline__ void cp_commit() {
    asm volatile("cp.async.commit_group;" ::: "memory");
}
template<int N>
__device__ __forceinline__ void cp_wait() {
    asm volatile("cp.async.wait_group %0;" :: "n"(N) : "memory");
}

__device__ __forceinline__ uint32_t smem_u32(const void* p) {
    uint32_t a;
    asm("{ .reg .u64 t; cvta.to.shared.u64 t, %1; cvt.u32.u64 %0, t; }"
        : "=r"(a) : "l"(p));
    return a;
}

__device__ __forceinline__ uint32_t pack_h2(float lo, float hi) {
    uint32_t p;
    asm("cvt.rn.f16x2.f32 %0, %1, %2;" : "=r"(p) : "f"(hi), "f"(lo));
    return p;
}

// ---------------- setup kernels ----------------------------------------------
__global__ void k_init(const float* __restrict__ fp, float* __restrict__ out) {
    int i = blockIdx.x * blockDim.x + threadIdx.x;
    if (i >= BDIM * NTRAJ * LAT) return;
    int c = i % LAT;
    int n = (i / LAT) % NTRAJ;
    int b = i / (LAT * NTRAJ);
    float v = fp[i];
    size_t idx = ((size_t)(b * NROWS + n)) * LAT + c;
    g_x[idx] = v;
    g_xin[idx] = __float2half(v);
    out[((((size_t)b * NTRAJ) + n) * TSTEPS + 0) * LAT + c] = v;
}

__global__ void k_mean(const float* __restrict__ fp) {
    int b = blockIdx.x;
    int d = threadIdx.x;
    const float* p = fp + (size_t)b * NTRAJ * LAT + d;
    float s = 0.f;
    for (int n = 0; n < NTRAJ; n++) s += p[(size_t)n * LAT];
    g_mean[b * LAT + d] = s * (1.0f / NTRAJ);
}

__global__ void k_cov(const float* __restrict__ fp) {
    int b  = blockIdx.z;
    int d0 = blockIdx.y * 16;
    int e0 = blockIdx.x * 16;
    int ty = threadIdx.y, tx = threadIdx.x;
    __shared__ float Ad[16][17];
    __shared__ float Ae[16][17];
    float md = g_mean[b * LAT + d0 + tx];
    float me = g_mean[b * LAT + e0 + tx];
    const float* base = fp + (size_t)b * NTRAJ * LAT;
    float acc = 0.f;
    for (int n0 = 0; n0 < NTRAJ; n0 += 16) {
        Ad[ty][tx] = base[(size_t)(n0 + ty) * LAT + d0 + tx] - md;
        Ae[ty][tx] = base[(size_t)(n0 + ty) * LAT + e0 + tx] - me;
        __syncthreads();
        #pragma unroll
        for (int k = 0; k < 16; k++)
            acc = fmaf(Ad[k][ty], Ae[k][tx], acc);
        __syncthreads();
    }
    g_cov[((size_t)(b * LAT + d0 + ty)) * LAT + e0 + tx] = acc;
}

__global__ void k_corr() {
    int i = blockIdx.x * blockDim.x + threadIdx.x;
    if (i >= BDIM * LAT * LAT) return;
    int e = i % LAT;
    int d = (i / LAT) % LAT;
    int b = i / (LAT * LAT);
    float c  = g_cov[i];
    float dd = g_cov[((size_t)(b * LAT + d)) * LAT + d];
    float de = g_cov[((size_t)(b * LAT + e)) * LAT + e];
    float v = c * rsqrtf(dd * de);
    size_t idx = ((size_t)(b * NROWS + NTRAJ + d)) * LAT + e;
    g_x[idx] = v;
    g_xin[idx] = __float2half(v);
}

__global__ void k_w1t(const float* __restrict__ W1) {
    int i = blockIdx.x * blockDim.x + threadIdx.x;
    if (i >= LAT * HID) return;
    int k = i / HID, n = i % HID;
    g_W1T[(size_t)n * LAT + k] = __float2half(W1[i]);
}
__global__ void k_w2t(const float* __restrict__ W2) {
    int i = blockIdx.x * blockDim.x + threadIdx.x;
    if (i >= HID * LAT) return;
    int k = i / LAT, n = i % LAT;
    g_W2T[(size_t)n * HID + k] = __float2half(W2[i]);
}

// ---------------- fp16 GEMM: 64x64 tile, 128 thr, cp.async + ldmatrix --------
// A [M,KDIM] fp16 row-major; B^T [N,KDIM] fp16 row-major. Warp tile 64x16.
// smem per stage: A 64 rows x 80B, B 64 rows x 80B (32 halfs payload/row).
// 3-stage cp.async pipeline, 1 __syncthreads per iter.
//
// IS_G1: A=g_xin (K=256), B=g_W1T, epilogue tanh(.+b1) -> g_h
// else : A=g_h   (K=1024), B=g_W2T, epilogue RK4 bookkeeping (mode 0/1/2)
#define STG_BYTES 10240   // 2 * 64 * 80

template<int KDIM, bool IS_G1>
__global__ __launch_bounds__(128, 5)
void k_mm(const float* __restrict__ b1v, const float* __restrict__ ts, int step,
          int mode, float cnext, float* __restrict__ out) {
    constexpr int NIT  = KDIM / 32;
    constexpr int ROWB = KDIM * 2;

    __shared__ __align__(16) char sm[3 * STG_BYTES];
    const uint32_t smB = smem_u32(sm);

    const int m0 = blockIdx.y * 64;
    const int n0 = blockIdx.x * 64;
    const int tid  = threadIdx.x;
    const int lane = tid & 31;
    const int wn   = tid >> 5;          // warp -> 16-wide n slice
    const int r  = lane >> 2;
    const int cq = lane & 3;

    // ldmatrix per-lane address parts
    const int sub = lane >> 3;
    const int rowPart = ((sub & 1) * 8 + (lane & 7));
    const int colPart = (sub >> 1) * 16;

    // cp.async mapping: 2 A rows + 2 B rows per thread per stage
    const int cRow = tid >> 2;          // 0..31 (+32)
    const int cSeg = tid & 3;

    const char* Ag = (const char*)(IS_G1 ? g_xin : g_h)
                   + (size_t)(m0 + cRow) * ROWB + cSeg * 16;
    const char* Bg = (const char*)(IS_G1 ? g_W1T : g_W2T)
                   + (size_t)(n0 + cRow) * ROWB + cSeg * 16;
    const uint32_t aDst0 = smB + cRow * 80 + cSeg * 16;
    const uint32_t bDst0 = smB + 5120 + cRow * 80 + cSeg * 16;

    auto copyStage = [&](int it, int s) {
        uint32_t so = (uint32_t)s * STG_BYTES;
        #pragma unroll
        for (int l = 0; l < 2; l++)
            cp16(aDst0 + so + l * 32 * 80, Ag + (size_t)(l * 32) * ROWB + it * 64);
        #pragma unroll
        for (int l = 0; l < 2; l++)
            cp16(bDst0 + so + l * 32 * 80, Bg + (size_t)(l * 32) * ROWB + it * 64);
        cp_commit();
    };

    float acc[4][2][4] = {};

    copyStage(0, 0);
    copyStage(1, 1);

    #pragma unroll 2
    for (int it = 0; it < NIT; it++) {
        if (it + 1 < NIT) cp_wait<1>(); else cp_wait<0>();
        __syncthreads();
        if (it + 2 < NIT) copyStage(it + 2, (it + 2) % 3);

        const uint32_t aB = smB + (uint32_t)(it % 3) * STG_BYTES;
        const uint32_t bB = aB + 5120;

        #pragma unroll
        for (int ks = 0; ks < 2; ks++) {
            uint32_t bq[4];
            ldsm4(bq, bB + (wn * 16 + rowPart) * 80 + ks * 32 + colPart);
            #pragma unroll
            for (int mt = 0; mt < 4; mt++) {
                uint32_t af[4];
                ldsm4(af, aB + (mt * 16 + rowPart) * 80 + ks * 32 + colPart);
                mma_fp16(acc[mt][0], af, bq[0], bq[2]);
                mma_fp16(acc[mt][1], af, bq[1], bq[3]);
            }
        }
    }

    // ---------------- epilogue ----------------
    if (IS_G1) {
        #pragma unroll
        for (int mt = 0; mt < 4; mt++) {
            int row0 = m0 + mt * 16 + r;
            #pragma unroll
            for (int nt = 0; nt < 2; nt++) {
                int col = n0 + wn * 16 + nt * 8 + 2 * cq;
                float bx = __ldg(b1v + col), by = __ldg(b1v + col + 1);
                float t0 = tanh_fast(acc[mt][nt][0] + bx);
                float t1 = tanh_fast(acc[mt][nt][1] + by);
                float t2 = tanh_fast(acc[mt][nt][2] + bx);
                float t3 = tanh_fast(acc[mt][nt][3] + by);
                *(uint32_t*)((char*)g_h + ((size_t)row0 * HID + col) * 2)
                    = pack_h2(t0, t1);
                *(uint32_t*)((char*)g_h + ((size_t)(row0 + 8) * HID + col) * 2)
                    = pack_h2(t2, t3);
            }
        }
    } else {
        const float dt = ts[step + 1] - ts[step];
        const float cn = cnext * dt;
        const float s6 = dt * (1.0f / 6.0f);

        #pragma unroll
        for (int mt = 0; mt < 4; mt++) {
            #pragma unroll
            for (int h = 0; h < 2; h++) {
                int row = m0 + mt * 16 + r + 8 * h;
                int b = row / NROWS;
                int n = row % NROWS;
                #pragma unroll
                for (int nt = 0; nt < 2; nt++) {
                    int col = n0 + wn * 16 + nt * 8 + 2 * cq;
                    float v0 = acc[mt][nt][2 * h + 0];
                    float v1 = acc[mt][nt][2 * h + 1];
                    size_t idx = (size_t)row * LAT + col;
                    if (mode == 0) {
                        g_ksum[idx] = v0;  g_ksum[idx + 1] = v1;
                        float xi0 = fmaf(cn, v0, g_x[idx]);
                        float xi1 = fmaf(cn, v1, g_x[idx + 1]);
                        *(uint32_t*)((char*)g_xin + idx * 2) = pack_h2(xi0, xi1);
                    } else if (mode == 1) {
                        g_ksum[idx]     += 2.f * v0;
                        g_ksum[idx + 1] += 2.f * v1;
                        float xi0 = fmaf(cn, v0, g_x[idx]);
                        float xi1 = fmaf(cn, v1, g_x[idx + 1]);
                        *(uint32_t*)((char*)g_xin + idx * 2) = pack_h2(xi0, xi1);
                    } else {
                        float x0 = g_x[idx] + s6 * (g_ksum[idx] + v0);
                        float x1 = g_x[idx + 1] + s6 * (g_ksum[idx + 1] + v1);
                        g_x[idx] = x0;   g_x[idx + 1] = x1;
                        *(uint32_t*)((char*)g_xin + idx * 2) = pack_h2(x0, x1);
                        if (n < NTRAJ) {
                            size_t o = ((((size_t)b * NTRAJ) + n) * TSTEPS
                                        + (step + 1)) * LAT + col;
                            out[o] = x0; out[o + 1] = x1;
                        }
                    }
                }
            }
        }
    }
}

// ---------------- launch ------------------------------------------------------
extern "C" void kernel_launch(void* const* d_in, const int* in_sizes, int n_in,
                              void* d_out, int out_size) {
    const float* fp = (const float*)d_in[0];
    const float* ts = (const float*)d_in[1];
    const float* W1 = (const float*)d_in[2];
    const float* b1 = (const float*)d_in[3];
    const float* W2 = (const float*)d_in[4];
    float* out = (float*)d_out;

    k_init<<<(BDIM * NTRAJ * LAT + 255) / 256, 256>>>(fp, out);
    k_mean<<<BDIM, LAT>>>(fp);
    k_cov<<<dim3(LAT / 16, LAT / 16, BDIM), dim3(16, 16)>>>(fp);
    k_corr<<<(BDIM * LAT * LAT + 255) / 256, 256>>>();
    k_w1t<<<(LAT * HID + 255) / 256, 256>>>(W1);
    k_w2t<<<(HID * LAT + 255) / 256, 256>>>(W2);

    dim3 g1(HID / 64, MTOT / 64);   // (16, 384) = 6144 blocks
    dim3 g2(LAT / 64, MTOT / 64);   // (4, 384)  = 1536 blocks

    for (int s = 0; s < TSTEPS - 1; s++) {
        // eval 1 -> k1: ksum = k1,  xin = x + 0.5*dt*k1
        k_mm<LAT,  true ><<<g1, 128>>>(b1, ts, s, 0, 0.0f, nullptr);
        k_mm<HID,  false><<<g2, 128>>>(nullptr, ts, s, 0, 0.5f, out);
        // eval 2 -> k2: ksum += 2*k2, xin = x + 0.5*dt*k2
        k_mm<LAT,  true ><<<g1, 128>>>(b1, ts, s, 0, 0.0f, nullptr);
        k_mm<HID,  false><<<g2, 128>>>(nullptr, ts, s, 1, 0.5f, out);
        // eval 3 -> k3: ksum += 2*k3, xin = x + dt*k3
        k_mm<LAT,  true ><<<g1, 128>>>(b1, ts, s, 0, 0.0f, nullptr);
        k_mm<HID,  false><<<g2, 128>>>(nullptr, ts, s, 1, 1.0f, out);
        // eval 4 -> k4: x += dt/6*(ksum + k4); write slice; xin = x_new
        k_mm<LAT,  true ><<<g1, 128>>>(b1, ts, s, 0, 0.0f, nullptr);
        k_mm<HID,  false><<<g2, 128>>>(nullptr, ts, s, 2, 0.0f, out);
    }
}

// round 8
// speedup vs baseline: 1.6067x; 1.6067x over previous
#include <cuda_runtime.h>
#include <cuda_fp16.h>
#include <math.h>
#include <stdint.h>

// Problem constants
#define BDIM   32
#define NTRAJ  512
#define LAT    256
#define HID    1024
#define TSTEPS 10
// The ODE is row-local: tanh(x@W1+b1)@W2 never couples rows. The corrcoef
// block (rows 512..767 per batch) is discarded by the final slice, so we
// only ever evolve the 512 trajectory rows per batch.
#define MTOT   (BDIM * NTRAJ)       // 16384 rows

// ---------------- scratch ----------------------------------------------------
__device__ __align__(16) float  g_x   [MTOT * LAT];   // committed state (fp32)
__device__ __align__(16) float  g_ksum[MTOT * LAT];   // weighted k accum (fp32)
__device__ __align__(16) __half g_xin [MTOT * LAT];   // next eval input (fp16)
__device__ __align__(16) __half g_h   [MTOT * HID];   // hidden (fp16)
__device__ __align__(16) __half g_W1T [HID * LAT];    // W1^T [n=1024][k=256]
__device__ __align__(16) __half g_W2T [LAT * HID];    // W2^T [n=256][k=1024]

// ---------------- helpers -----------------------------------------------------
__device__ __forceinline__ float tanh_fast(float x) {
    float y;
    asm("tanh.approx.f32 %0, %1;" : "=f"(y) : "f"(x));
    return y;
}

__device__ __forceinline__ void mma_fp16(float* d, const uint32_t* a,
                                         uint32_t b0, uint32_t b1) {
    asm("mma.sync.aligned.m16n8k16.row.col.f32.f16.f16.f32 "
        "{%0,%1,%2,%3},{%4,%5,%6,%7},{%8,%9},{%0,%1,%2,%3};"
        : "+f"(d[0]), "+f"(d[1]), "+f"(d[2]), "+f"(d[3])
        : "r"(a[0]), "r"(a[1]), "r"(a[2]), "r"(a[3]), "r"(b0), "r"(b1));
}

__device__ __forceinline__ void ldsm4(uint32_t* r, uint32_t addr) {
    asm volatile("ldmatrix.sync.aligned.m8n8.x4.shared.b16 {%0,%1,%2,%3}, [%4];"
                 : "=r"(r[0]), "=r"(r[1]), "=r"(r[2]), "=r"(r[3]) : "r"(addr));
}

__device__ __forceinline__ void cp16(uint32_t dst, const void* src) {
    asm volatile("cp.async.cg.shared.global [%0], [%1], 16;"
                 :: "r"(dst), "l"(src));
}
__device__ __forceinline__ void cp_commit() {
    asm volatile("cp.async.commit_group;" ::: "memory");
}
template<int N>
__device__ __forceinline__ void cp_wait() {
    asm volatile("cp.async.wait_group %0;" :: "n"(N) : "memory");
}

__device__ __forceinline__ uint32_t smem_u32(const void* p) {
    uint32_t a;
    asm("{ .reg .u64 t; cvta.to.shared.u64 t, %1; cvt.u32.u64 %0, t; }"
        : "=r"(a) : "l"(p));
    return a;
}

__device__ __forceinline__ uint32_t pack_h2(float lo, float hi) {
    uint32_t p;
    asm("cvt.rn.f16x2.f32 %0, %1, %2;" : "=r"(p) : "f"(hi), "f"(lo));
    return p;
}

// ---------------- setup kernels ----------------------------------------------
// state rows are exactly first_point's layout (B*NTRAJ, LAT)
__global__ void k_init(const float* __restrict__ fp, float* __restrict__ out) {
    int i = blockIdx.x * blockDim.x + threadIdx.x;
    if (i >= MTOT * LAT) return;
    int c = i % LAT;
    int row = i / LAT;          // = b*NTRAJ + n
    float v = fp[i];
    g_x[i] = v;
    g_xin[i] = __float2half(v);
    out[((size_t)row * TSTEPS + 0) * LAT + c] = v;
}

__global__ void k_w1t(const float* __restrict__ W1) {
    int i = blockIdx.x * blockDim.x + threadIdx.x;
    if (i >= LAT * HID) return;
    int k = i / HID, n = i % HID;
    g_W1T[(size_t)n * LAT + k] = __float2half(W1[i]);
}
__global__ void k_w2t(const float* __restrict__ W2) {
    int i = blockIdx.x * blockDim.x + threadIdx.x;
    if (i >= HID * LAT) return;
    int k = i / LAT, n = i % LAT;
    g_W2T[(size_t)n * HID + k] = __float2half(W2[i]);
}

// ---------------- fp16 GEMM: 64x64 tile, 128 thr, cp.async + ldmatrix --------
// A [M,KDIM] fp16 row-major; B^T [N,KDIM] fp16 row-major. Warp tile 64x16.
// smem per stage: A 64 rows x 80B, B 64 rows x 80B (32 halfs payload/row).
// 3-stage cp.async pipeline, 1 __syncthreads per iter.
//
// IS_G1: A=g_xin (K=256), B=g_W1T, epilogue tanh(.+b1) -> g_h
// else : A=g_h   (K=1024), B=g_W2T, epilogue RK4 bookkeeping (mode 0/1/2)
#define STG_BYTES 10240   // 2 * 64 * 80

template<int KDIM, bool IS_G1>
__global__ __launch_bounds__(128, 5)
void k_mm(const float* __restrict__ b1v, const float* __restrict__ ts, int step,
          int mode, float cnext, float* __restrict__ out) {
    constexpr int NIT  = KDIM / 32;
    constexpr int ROWB = KDIM * 2;

    __shared__ __align__(16) char sm[3 * STG_BYTES];
    const uint32_t smB = smem_u32(sm);

    const int m0 = blockIdx.y * 64;
    const int n0 = blockIdx.x * 64;
    const int tid  = threadIdx.x;
    const int lane = tid & 31;
    const int wn   = tid >> 5;          // warp -> 16-wide n slice
    const int r  = lane >> 2;
    const int cq = lane & 3;

    // ldmatrix per-lane address parts
    const int sub = lane >> 3;
    const int rowPart = ((sub & 1) * 8 + (lane & 7));
    const int colPart = (sub >> 1) * 16;

    // cp.async mapping: 2 A rows + 2 B rows per thread per stage
    const int cRow = tid >> 2;          // 0..31 (+32)
    const int cSeg = tid & 3;

    const char* Ag = (const char*)(IS_G1 ? g_xin : g_h)
                   + (size_t)(m0 + cRow) * ROWB + cSeg * 16;
    const char* Bg = (const char*)(IS_G1 ? g_W1T : g_W2T)
                   + (size_t)(n0 + cRow) * ROWB + cSeg * 16;
    const uint32_t aDst0 = smB + cRow * 80 + cSeg * 16;
    const uint32_t bDst0 = smB + 5120 + cRow * 80 + cSeg * 16;

    auto copyStage = [&](int it, int s) {
        uint32_t so = (uint32_t)s * STG_BYTES;
        #pragma unroll
        for (int l = 0; l < 2; l++)
            cp16(aDst0 + so + l * 32 * 80, Ag + (size_t)(l * 32) * ROWB + it * 64);
        #pragma unroll
        for (int l = 0; l < 2; l++)
            cp16(bDst0 + so + l * 32 * 80, Bg + (size_t)(l * 32) * ROWB + it * 64);
        cp_commit();
    };

    float acc[4][2][4] = {};

    copyStage(0, 0);
    copyStage(1, 1);

    #pragma unroll 2
    for (int it = 0; it < NIT; it++) {
        if (it + 1 < NIT) cp_wait<1>(); else cp_wait<0>();
        __syncthreads();
        if (it + 2 < NIT) copyStage(it + 2, (it + 2) % 3);

        const uint32_t aB = smB + (uint32_t)(it % 3) * STG_BYTES;
        const uint32_t bB = aB + 5120;

        #pragma unroll
        for (int ks = 0; ks < 2; ks++) {
            uint32_t bq[4];
            ldsm4(bq, bB + (wn * 16 + rowPart) * 80 + ks * 32 + colPart);
            #pragma unroll
            for (int mt = 0; mt < 4; mt++) {
                uint32_t af[4];
                ldsm4(af, aB + (mt * 16 + rowPart) * 80 + ks * 32 + colPart);
                mma_fp16(acc[mt][0], af, bq[0], bq[2]);
                mma_fp16(acc[mt][1], af, bq[1], bq[3]);
            }
        }
    }

    // ---------------- epilogue ----------------
    if (IS_G1) {
        #pragma unroll
        for (int mt = 0; mt < 4; mt++) {
            int row0 = m0 + mt * 16 + r;
            #pragma unroll
            for (int nt = 0; nt < 2; nt++) {
                int col = n0 + wn * 16 + nt * 8 + 2 * cq;
                float bx = __ldg(b1v + col), by = __ldg(b1v + col + 1);
                float t0 = tanh_fast(acc[mt][nt][0] + bx);
                float t1 = tanh_fast(acc[mt][nt][1] + by);
                float t2 = tanh_fast(acc[mt][nt][2] + bx);
                float t3 = tanh_fast(acc[mt][nt][3] + by);
                *(uint32_t*)((char*)g_h + ((size_t)row0 * HID + col) * 2)
                    = pack_h2(t0, t1);
                *(uint32_t*)((char*)g_h + ((size_t)(row0 + 8) * HID + col) * 2)
                    = pack_h2(t2, t3);
            }
        }
    } else {
        const float dt = ts[step + 1] - ts[step];
        const float cn = cnext * dt;
        const float s6 = dt * (1.0f / 6.0f);

        #pragma unroll
        for (int mt = 0; mt < 4; mt++) {
            #pragma unroll
            for (int h = 0; h < 2; h++) {
                int row = m0 + mt * 16 + r + 8 * h;   // = b*NTRAJ + n
                #pragma unroll
                for (int nt = 0; nt < 2; nt++) {
                    int col = n0 + wn * 16 + nt * 8 + 2 * cq;
                    float v0 = acc[mt][nt][2 * h + 0];
                    float v1 = acc[mt][nt][2 * h + 1];
                    size_t idx = (size_t)row * LAT + col;
                    if (mode == 0) {
                        g_ksum[idx] = v0;  g_ksum[idx + 1] = v1;
                        float xi0 = fmaf(cn, v0, g_x[idx]);
                        float xi1 = fmaf(cn, v1, g_x[idx + 1]);
                        *(uint32_t*)((char*)g_xin + idx * 2) = pack_h2(xi0, xi1);
                    } else if (mode == 1) {
                        g_ksum[idx]     += 2.f * v0;
                        g_ksum[idx + 1] += 2.f * v1;
                        float xi0 = fmaf(cn, v0, g_x[idx]);
                        float xi1 = fmaf(cn, v1, g_x[idx + 1]);
                        *(uint32_t*)((char*)g_xin + idx * 2) = pack_h2(xi0, xi1);
                    } else {
                        float x0 = g_x[idx] + s6 * (g_ksum[idx] + v0);
                        float x1 = g_x[idx + 1] + s6 * (g_ksum[idx + 1] + v1);
                        g_x[idx] = x0;   g_x[idx + 1] = x1;
                        *(uint32_t*)((char*)g_xin + idx * 2) = pack_h2(x0, x1);
                        size_t o = ((size_t)row * TSTEPS + (step + 1)) * LAT + col;
                        out[o] = x0; out[o + 1] = x1;
                    }
                }
            }
        }
    }
}

// ---------------- launch ------------------------------------------------------
extern "C" void kernel_launch(void* const* d_in, const int* in_sizes, int n_in,
                              void* d_out, int out_size) {
    const float* fp = (const float*)d_in[0];
    const float* ts = (const float*)d_in[1];
    const float* W1 = (const float*)d_in[2];
    const float* b1 = (const float*)d_in[3];
    const float* W2 = (const float*)d_in[4];
    float* out = (float*)d_out;

    k_init<<<(MTOT * LAT + 255) / 256, 256>>>(fp, out);
    k_w1t<<<(LAT * HID + 255) / 256, 256>>>(W1);
    k_w2t<<<(HID * LAT + 255) / 256, 256>>>(W2);

    dim3 g1(HID / 64, MTOT / 64);   // (16, 256) = 4096 blocks
    dim3 g2(LAT / 64, MTOT / 64);   // (4, 256)  = 1024 blocks

    for (int s = 0; s < TSTEPS - 1; s++) {
        // eval 1 -> k1: ksum = k1,  xin = x + 0.5*dt*k1
        k_mm<LAT,  true ><<<g1, 128>>>(b1, ts, s, 0, 0.0f, nullptr);
        k_mm<HID,  false><<<g2, 128>>>(nullptr, ts, s, 0, 0.5f, out);
        // eval 2 -> k2: ksum += 2*k2, xin = x + 0.5*dt*k2
        k_mm<LAT,  true ><<<g1, 128>>>(b1, ts, s, 0, 0.0f, nullptr);
        k_mm<HID,  false><<<g2, 128>>>(nullptr, ts, s, 1, 0.5f, out);
        // eval 3 -> k3: ksum += 2*k3, xin = x + dt*k3
        k_mm<LAT,  true ><<<g1, 128>>>(b1, ts, s, 0, 0.0f, nullptr);
        k_mm<HID,  false><<<g2, 128>>>(nullptr, ts, s, 1, 1.0f, out);
        // eval 4 -> k4: x += dt/6*(ksum + k4); write slice; xin = x_new
        k_mm<LAT,  true ><<<g1, 128>>>(b1, ts, s, 0, 0.0f, nullptr);
        k_mm<HID,  false><<<g2, 128>>>(nullptr, ts, s, 2, 0.0f, out);
    }
}

// round 9
// speedup vs baseline: 1.6978x; 1.0567x over previous
#include <cuda_runtime.h>
#include <cuda_fp16.h>
#include <math.h>
#include <stdint.h>

// Problem constants
#define BDIM   32
#define NTRAJ  512
#define LAT    256
#define HID    1024
#define TSTEPS 10
// The ODE is row-local: tanh(x@W1+b1)@W2 never couples rows. The corrcoef
// block (rows 512..767 per batch) is discarded by the final slice, so we
// only evolve the 512 trajectory rows per batch.
#define MTOT   (BDIM * NTRAJ)       // 16384 rows

// ---------------- scratch ----------------------------------------------------
__device__ __align__(16) float  g_x   [MTOT * LAT];   // committed state (fp32)
__device__ __align__(16) float  g_ksum[MTOT * LAT];   // weighted k accum (fp32)
__device__ __align__(16) __half g_xin [MTOT * LAT];   // next eval input (fp16)
__device__ __align__(16) __half g_h   [MTOT * HID];   // hidden (fp16)
__device__ __align__(16) __half g_W1T [HID * LAT];    // W1^T [n=1024][k=256]
__device__ __align__(16) __half g_W2T [LAT * HID];    // W2^T [n=256][k=1024]

// ---------------- helpers -----------------------------------------------------
__device__ __forceinline__ float tanh_fast(float x) {
    float y;
    asm("tanh.approx.f32 %0, %1;" : "=f"(y) : "f"(x));
    return y;
}

__device__ __forceinline__ void mma_fp16(float* d, const uint32_t* a,
                                         uint32_t b0, uint32_t b1) {
    asm("mma.sync.aligned.m16n8k16.row.col.f32.f16.f16.f32 "
        "{%0,%1,%2,%3},{%4,%5,%6,%7},{%8,%9},{%0,%1,%2,%3};"
        : "+f"(d[0]), "+f"(d[1]), "+f"(d[2]), "+f"(d[3])
        : "r"(a[0]), "r"(a[1]), "r"(a[2]), "r"(a[3]), "r"(b0), "r"(b1));
}

__device__ __forceinline__ void ldsm4(uint32_t* r, uint32_t addr) {
    asm volatile("ldmatrix.sync.aligned.m8n8.x4.shared.b16 {%0,%1,%2,%3}, [%4];"
                 : "=r"(r[0]), "=r"(r[1]), "=r"(r[2]), "=r"(r[3]) : "r"(addr));
}

__device__ __forceinline__ void cp16(uint32_t dst, const void* src) {
    asm volatile("cp.async.cg.shared.global [%0], [%1], 16;"
                 :: "r"(dst), "l"(src));
}
__device__ __forceinline__ void cp_commit() {
    asm volatile("cp.async.commit_group;" ::: "memory");
}
template<int N>
__device__ __forceinline__ void cp_wait() {
    asm volatile("cp.async.wait_group %0;" :: "n"(N) : "memory");
}

__device__ __forceinline__ uint32_t smem_u32(const void* p) {
    uint32_t a;
    asm("{ .reg .u64 t; cvta.to.shared.u64 t, %1; cvt.u32.u64 %0, t; }"
        : "=r"(a) : "l"(p));
    return a;
}

__device__ __forceinline__ uint32_t pack_h2(float lo, float hi) {
    uint32_t p;
    asm("cvt.rn.f16x2.f32 %0, %1, %2;" : "=r"(p) : "f"(hi), "f"(lo));
    return p;
}

// ---------------- setup kernels ----------------------------------------------
__global__ void k_init(const float* __restrict__ fp, float* __restrict__ out) {
    int i = blockIdx.x * blockDim.x + threadIdx.x;
    if (i >= MTOT * LAT) return;
    int c = i % LAT;
    int row = i / LAT;          // = b*NTRAJ + n
    float v = fp[i];
    g_x[i] = v;
    g_xin[i] = __float2half(v);
    out[((size_t)row * TSTEPS + 0) * LAT + c] = v;
}

__global__ void k_w1t(const float* __restrict__ W1) {
    int i = blockIdx.x * blockDim.x + threadIdx.x;
    if (i >= LAT * HID) return;
    int k = i / HID, n = i % HID;
    g_W1T[(size_t)n * LAT + k] = __float2half(W1[i]);
}
__global__ void k_w2t(const float* __restrict__ W2) {
    int i = blockIdx.x * blockDim.x + threadIdx.x;
    if (i >= HID * LAT) return;
    int k = i / LAT, n = i % LAT;
    g_W2T[(size_t)n * HID + k] = __float2half(W2[i]);
}

// ---------------- fp16 GEMM: 128x128 tile, 256 thr, warp 64x32 ---------------
// A [M,KDIM] fp16 row-major; B^T [N,KDIM] fp16 row-major.
// smem per stage: A 128 rows x 80B + B 128 rows x 80B (32 halfs payload/row).
// 3-stage cp.async pipeline, ldmatrix.x4 fragment loads.
//
// IS_G1: A=g_xin (K=256), B=g_W1T, epilogue tanh(.+b1) -> g_h
// else : A=g_h   (K=1024), B=g_W2T, epilogue RK4 bookkeeping (mode 0/1/2)
#define STG_BYTES 20480   // 2 * 128 * 80

template<int KDIM, bool IS_G1>
__global__ __launch_bounds__(256, 2)
void k_mm(const float* __restrict__ b1v, const float* __restrict__ ts, int step,
          int mode, float cnext, float* __restrict__ out) {
    constexpr int NIT  = KDIM / 32;
    constexpr int ROWB = KDIM * 2;

    __shared__ __align__(16) char sm[3 * STG_BYTES];
    const uint32_t smB = smem_u32(sm);

    const int m0 = blockIdx.y * 128;
    const int n0 = blockIdx.x * 128;
    const int tid  = threadIdx.x;
    const int lane = tid & 31;
    const int warp = tid >> 5;
    const int wm = warp & 1;            // m half (64 rows)
    const int wn = warp >> 1;           // n quarter (32 cols)
    const int r  = lane >> 2;
    const int cq = lane & 3;

    // ldmatrix per-lane address parts
    const int sub = lane >> 3;
    const int rowPart = ((sub & 1) * 8 + (lane & 7));
    const int colPart = (sub >> 1) * 16;

    // cp.async mapping: 2 A rows + 2 B rows per thread per stage
    const int cRow = tid >> 2;          // 0..63 (+64)
    const int cSeg = tid & 3;

    const char* Ag = (const char*)(IS_G1 ? g_xin : g_h)
                   + (size_t)(m0 + cRow) * ROWB + cSeg * 16;
    const char* Bg = (const char*)(IS_G1 ? g_W1T : g_W2T)
                   + (size_t)(n0 + cRow) * ROWB + cSeg * 16;
    const uint32_t aDst0 = smB + cRow * 80 + cSeg * 16;
    const uint32_t bDst0 = smB + 10240 + cRow * 80 + cSeg * 16;

    auto copyStage = [&](int it, int s) {
        uint32_t so = (uint32_t)s * STG_BYTES;
        #pragma unroll
        for (int l = 0; l < 2; l++)
            cp16(aDst0 + so + l * 64 * 80, Ag + (size_t)(l * 64) * ROWB + it * 64);
        #pragma unroll
        for (int l = 0; l < 2; l++)
            cp16(bDst0 + so + l * 64 * 80, Bg + (size_t)(l * 64) * ROWB + it * 64);
        cp_commit();
    };

    float acc[4][4][4] = {};

    copyStage(0, 0);
    copyStage(1, 1);

    #pragma unroll 1
    for (int it = 0; it < NIT; it++) {
        if (it + 1 < NIT) cp_wait<1>(); else cp_wait<0>();
        __syncthreads();
        if (it + 2 < NIT) copyStage(it + 2, (it + 2) % 3);

        const uint32_t aB = smB + (uint32_t)(it % 3) * STG_BYTES;
        const uint32_t bB = aB + 10240;

        #pragma unroll
        for (int ks = 0; ks < 2; ks++) {
            // B fragments: 32 n-cols (two ldsm.x4 -> 4 n-octets)
            uint32_t bq0[4], bq1[4];
            ldsm4(bq0, bB + (wn * 32 + rowPart) * 80 + ks * 32 + colPart);
            ldsm4(bq1, bB + (wn * 32 + 16 + rowPart) * 80 + ks * 32 + colPart);
            #pragma unroll
            for (int mt = 0; mt < 4; mt++) {
                uint32_t af[4];
                ldsm4(af, aB + (wm * 64 + mt * 16 + rowPart) * 80 + ks * 32 + colPart);
                mma_fp16(acc[mt][0], af, bq0[0], bq0[2]);
                mma_fp16(acc[mt][1], af, bq0[1], bq0[3]);
                mma_fp16(acc[mt][2], af, bq1[0], bq1[2]);
                mma_fp16(acc[mt][3], af, bq1[1], bq1[3]);
            }
        }
    }

    // ---------------- epilogue ----------------
    if (IS_G1) {
        #pragma unroll
        for (int mt = 0; mt < 4; mt++) {
            int row0 = m0 + wm * 64 + mt * 16 + r;
            #pragma unroll
            for (int nt = 0; nt < 4; nt++) {
                int col = n0 + wn * 32 + nt * 8 + 2 * cq;
                float bx = __ldg(b1v + col), by = __ldg(b1v + col + 1);
                float t0 = tanh_fast(acc[mt][nt][0] + bx);
                float t1 = tanh_fast(acc[mt][nt][1] + by);
                float t2 = tanh_fast(acc[mt][nt][2] + bx);
                float t3 = tanh_fast(acc[mt][nt][3] + by);
                *(uint32_t*)((char*)g_h + ((size_t)row0 * HID + col) * 2)
                    = pack_h2(t0, t1);
                *(uint32_t*)((char*)g_h + ((size_t)(row0 + 8) * HID + col) * 2)
                    = pack_h2(t2, t3);
            }
        }
    } else {
        const float dt = ts[step + 1] - ts[step];
        const float cn = cnext * dt;
        const float s6 = dt * (1.0f / 6.0f);

        #pragma unroll
        for (int mt = 0; mt < 4; mt++) {
            #pragma unroll
            for (int h = 0; h < 2; h++) {
                int row = m0 + wm * 64 + mt * 16 + r + 8 * h;   // = b*NTRAJ + n
                #pragma unroll
                for (int nt = 0; nt < 4; nt++) {
                    int col = n0 + wn * 32 + nt * 8 + 2 * cq;
                    float v0 = acc[mt][nt][2 * h + 0];
                    float v1 = acc[mt][nt][2 * h + 1];
                    size_t idx = (size_t)row * LAT + col;
                    if (mode == 0) {
                        g_ksum[idx] = v0;  g_ksum[idx + 1] = v1;
                        float xi0 = fmaf(cn, v0, g_x[idx]);
                        float xi1 = fmaf(cn, v1, g_x[idx + 1]);
                        *(uint32_t*)((char*)g_xin + idx * 2) = pack_h2(xi0, xi1);
                    } else if (mode == 1) {
                        g_ksum[idx]     += 2.f * v0;
                        g_ksum[idx + 1] += 2.f * v1;
                        float xi0 = fmaf(cn, v0, g_x[idx]);
                        float xi1 = fmaf(cn, v1, g_x[idx + 1]);
                        *(uint32_t*)((char*)g_xin + idx * 2) = pack_h2(xi0, xi1);
                    } else {
                        float x0 = g_x[idx] + s6 * (g_ksum[idx] + v0);
                        float x1 = g_x[idx + 1] + s6 * (g_ksum[idx + 1] + v1);
                        g_x[idx] = x0;   g_x[idx + 1] = x1;
                        *(uint32_t*)((char*)g_xin + idx * 2) = pack_h2(x0, x1);
                        size_t o = ((size_t)row * TSTEPS + (step + 1)) * LAT + col;
                        out[o] = x0; out[o + 1] = x1;
                    }
                }
            }
        }
    }
}

// ---------------- launch ------------------------------------------------------
extern "C" void kernel_launch(void* const* d_in, const int* in_sizes, int n_in,
                              void* d_out, int out_size) {
    const float* fp = (const float*)d_in[0];
    const float* ts = (const float*)d_in[1];
    const float* W1 = (const float*)d_in[2];
    const float* b1 = (const float*)d_in[3];
    const float* W2 = (const float*)d_in[4];
    float* out = (float*)d_out;

    k_init<<<(MTOT * LAT + 255) / 256, 256>>>(fp, out);
    k_w1t<<<(LAT * HID + 255) / 256, 256>>>(W1);
    k_w2t<<<(HID * LAT + 255) / 256, 256>>>(W2);

    dim3 g1(HID / 128, MTOT / 128);   // (8, 128) = 1024 blocks
    dim3 g2(LAT / 128, MTOT / 128);   // (2, 128) = 256 blocks

    for (int s = 0; s < TSTEPS - 1; s++) {
        // eval 1 -> k1: ksum = k1,  xin = x + 0.5*dt*k1
        k_mm<LAT,  true ><<<g1, 256>>>(b1, ts, s, 0, 0.0f, nullptr);
        k_mm<HID,  false><<<g2, 256>>>(nullptr, ts, s, 0, 0.5f, out);
        // eval 2 -> k2: ksum += 2*k2, xin = x + 0.5*dt*k2
        k_mm<LAT,  true ><<<g1, 256>>>(b1, ts, s, 0, 0.0f, nullptr);
        k_mm<HID,  false><<<g2, 256>>>(nullptr, ts, s, 1, 0.5f, out);
        // eval 3 -> k3: ksum += 2*k3, xin = x + dt*k3
        k_mm<LAT,  true ><<<g1, 256>>>(b1, ts, s, 0, 0.0f, nullptr);
        k_mm<HID,  false><<<g2, 256>>>(nullptr, ts, s, 1, 1.0f, out);
        // eval 4 -> k4: x += dt/6*(ksum + k4); write slice; xin = x_new
        k_mm<LAT,  true ><<<g1, 256>>>(b1, ts, s, 0, 0.0f, nullptr);
        k_mm<HID,  false><<<g2, 256>>>(nullptr, ts, s, 2, 0.0f, out);
    }
}

// round 10
// speedup vs baseline: 1.8452x; 1.0868x over previous
#include <cuda_runtime.h>
#include <cuda_fp16.h>
#include <math.h>
#include <stdint.h>

// Problem constants
#define BDIM   32
#define NTRAJ  512
#define LAT    256
#define HID    1024
#define TSTEPS 10
// The ODE is row-local: tanh(x@W1+b1)@W2 never couples rows. The corrcoef
// block (rows 512..767 per batch) is discarded by the final slice, so we
// only evolve the 512 trajectory rows per batch.
#define MTOT   (BDIM * NTRAJ)       // 16384 rows

// ---------------- scratch ----------------------------------------------------
__device__ __align__(16) float  g_x   [MTOT * LAT];   // committed state (fp32)
__device__ __align__(16) float  g_ksum[MTOT * LAT];   // weighted k accum (fp32)
__device__ __align__(16) __half g_xin [MTOT * LAT];   // next eval input (fp16)
__device__ __align__(16) __half g_h   [MTOT * HID];   // hidden (fp16)
__device__ __align__(16) __half g_W1T [HID * LAT];    // W1^T [n=1024][k=256]
__device__ __align__(16) __half g_W2T [LAT * HID];    // W2^T [n=256][k=1024]

// ---------------- helpers -----------------------------------------------------
__device__ __forceinline__ float tanh_fast(float x) {
    float y;
    asm("tanh.approx.f32 %0, %1;" : "=f"(y) : "f"(x));
    return y;
}

__device__ __forceinline__ void mma_fp16(float* d, const uint32_t* a,
                                         uint32_t b0, uint32_t b1) {
    asm("mma.sync.aligned.m16n8k16.row.col.f32.f16.f16.f32 "
        "{%0,%1,%2,%3},{%4,%5,%6,%7},{%8,%9},{%0,%1,%2,%3};"
        : "+f"(d[0]), "+f"(d[1]), "+f"(d[2]), "+f"(d[3])
        : "r"(a[0]), "r"(a[1]), "r"(a[2]), "r"(a[3]), "r"(b0), "r"(b1));
}

__device__ __forceinline__ void ldsm4(uint32_t* r, uint32_t addr) {
    asm volatile("ldmatrix.sync.aligned.m8n8.x4.shared.b16 {%0,%1,%2,%3}, [%4];"
                 : "=r"(r[0]), "=r"(r[1]), "=r"(r[2]), "=r"(r[3]) : "r"(addr));
}

__device__ __forceinline__ void cp16(uint32_t dst, const void* src) {
    asm volatile("cp.async.cg.shared.global [%0], [%1], 16;"
                 :: "r"(dst), "l"(src));
}
__device__ __forceinline__ void cp_commit() {
    asm volatile("cp.async.commit_group;" ::: "memory");
}
template<int N>
__device__ __forceinline__ void cp_wait() {
    asm volatile("cp.async.wait_group %0;" :: "n"(N) : "memory");
}

__device__ __forceinline__ uint32_t smem_u32(const void* p) {
    uint32_t a;
    asm("{ .reg .u64 t; cvta.to.shared.u64 t, %1; cvt.u32.u64 %0, t; }"
        : "=r"(a) : "l"(p));
    return a;
}

__device__ __forceinline__ uint32_t pack_h2(float lo, float hi) {
    uint32_t p;
    asm("cvt.rn.f16x2.f32 %0, %1, %2;" : "=r"(p) : "f"(hi), "f"(lo));
    return p;
}

// ---------------- setup kernels ----------------------------------------------
__global__ void k_init(const float* __restrict__ fp, float* __restrict__ out) {
    int i = blockIdx.x * blockDim.x + threadIdx.x;
    if (i >= MTOT * LAT) return;
    int c = i % LAT;
    int row = i / LAT;          // = b*NTRAJ + n
    float v = fp[i];
    g_x[i] = v;
    g_xin[i] = __float2half(v);
    out[((size_t)row * TSTEPS + 0) * LAT + c] = v;
}

__global__ void k_w1t(const float* __restrict__ W1) {
    int i = blockIdx.x * blockDim.x + threadIdx.x;
    if (i >= LAT * HID) return;
    int k = i / HID, n = i % HID;
    g_W1T[(size_t)n * LAT + k] = __float2half(W1[i]);
}
__global__ void k_w2t(const float* __restrict__ W2) {
    int i = blockIdx.x * blockDim.x + threadIdx.x;
    if (i >= HID * LAT) return;
    int k = i / LAT, n = i % LAT;
    g_W2T[(size_t)n * HID + k] = __float2half(W2[i]);
}

// ---------------- fp16 GEMM: 128x128 tile, 256 thr, warp 64x32 ---------------
// k-chunk = 64 halfs per stage (128B payload/row, 144B padded rows).
// 3-stage cp.async pipeline, ldmatrix.x4, software-pipelined fragments:
// B double-buffered across k16 steps, A double-buffered across mt.
//
// IS_G1: A=g_xin (K=256), B=g_W1T, epilogue tanh(.+b1) -> g_h
// else : A=g_h   (K=1024), B=g_W2T, epilogue RK4 bookkeeping (mode 0/1/2)
#define ROWP      144                  // padded smem row bytes
#define TILE_B    (128 * ROWP)         // one operand tile (18432 B)
#define STG_BYTES (2 * TILE_B)         // A + B per stage (36864 B)
#define SMEM_TOT  (3 * STG_BYTES)      // 110592 B

template<int KDIM, bool IS_G1>
__global__ __launch_bounds__(256, 2)
void k_mm(const float* __restrict__ b1v, const float* __restrict__ ts, int step,
          int mode, float cnext, float* __restrict__ out) {
    constexpr int NIT  = KDIM / 64;
    constexpr int ROWB = KDIM * 2;

    extern __shared__ __align__(16) char sm[];
    const uint32_t smB = smem_u32(sm);

    const int m0 = blockIdx.y * 128;
    const int n0 = blockIdx.x * 128;
    const int tid  = threadIdx.x;
    const int lane = tid & 31;
    const int warp = tid >> 5;
    const int wm = warp & 1;            // m half (64 rows)
    const int wn = warp >> 1;           // n quarter (32 cols)
    const int r  = lane >> 2;
    const int cq = lane & 3;

    // ldmatrix per-lane address parts
    const int sub = lane >> 3;
    const int rowPart = ((sub & 1) * 8 + (lane & 7));
    const int colPart = (sub >> 1) * 16;

    // cp.async mapping: 4 A + 4 B cp16 per thread per stage
    // element e = o*256 + tid -> row = e>>3 (0..127), seg = e&7 (16B units)
    const int cRow0 = tid >> 3;
    const int cSeg  = tid & 7;

    const char* Ag = (const char*)(IS_G1 ? g_xin : g_h)
                   + (size_t)m0 * ROWB + cSeg * 16;
    const char* Bg = (const char*)(IS_G1 ? g_W1T : g_W2T)
                   + (size_t)n0 * ROWB + cSeg * 16;

    auto copyStage = [&](int it, int s) {
        uint32_t so = smB + (uint32_t)s * STG_BYTES;
        #pragma unroll
        for (int o = 0; o < 4; o++) {
            int row = cRow0 + o * 32;
            cp16(so + row * ROWP + cSeg * 16,
                 Ag + (size_t)row * ROWB + it * 128);
        }
        #pragma unroll
        for (int o = 0; o < 4; o++) {
            int row = cRow0 + o * 32;
            cp16(so + TILE_B + row * ROWP + cSeg * 16,
                 Bg + (size_t)row * ROWB + it * 128);
        }
        cp_commit();
    };

    float acc[4][4][4] = {};

    copyStage(0, 0);
    copyStage(1, 1);

    #pragma unroll 1
    for (int it = 0; it < NIT; it++) {
        if (it + 1 < NIT) cp_wait<1>(); else cp_wait<0>();
        __syncthreads();
        if (it + 2 < NIT) copyStage(it + 2, (it + 2) % 3);

        const uint32_t aBase = smB + (uint32_t)(it % 3) * STG_BYTES
                             + (wm * 64 + rowPart) * ROWP + colPart;
        const uint32_t bBase = smB + (uint32_t)(it % 3) * STG_BYTES + TILE_B
                             + (wn * 32 + rowPart) * ROWP + colPart;

        uint32_t bq[2][8], af[2][4];
        ldsm4(bq[0],     bBase);
        ldsm4(bq[0] + 4, bBase + 16 * ROWP);
        ldsm4(af[0],     aBase);

        #pragma unroll
        for (int kq = 0; kq < 4; kq++) {
            const int kb = kq & 1;
            #pragma unroll
            for (int mt = 0; mt < 4; mt++) {
                if (mt < 3) {
                    ldsm4(af[(mt + 1) & 1], aBase + (mt + 1) * (16 * ROWP) + kq * 32);
                } else if (kq < 3) {
                    ldsm4(bq[kb ^ 1],     bBase + (kq + 1) * 32);
                    ldsm4(bq[kb ^ 1] + 4, bBase + 16 * ROWP + (kq + 1) * 32);
                    ldsm4(af[0],          aBase + (kq + 1) * 32);
                }
                const uint32_t* B = bq[kb];
                const uint32_t* A = af[mt & 1];
                mma_fp16(acc[mt][0], A, B[0], B[2]);
                mma_fp16(acc[mt][1], A, B[1], B[3]);
                mma_fp16(acc[mt][2], A, B[4], B[6]);
                mma_fp16(acc[mt][3], A, B[5], B[7]);
            }
        }
    }

    // ---------------- epilogue ----------------
    if (IS_G1) {
        #pragma unroll
        for (int mt = 0; mt < 4; mt++) {
            int row0 = m0 + wm * 64 + mt * 16 + r;
            #pragma unroll
            for (int nt = 0; nt < 4; nt++) {
                int col = n0 + wn * 32 + nt * 8 + 2 * cq;
                float bx = __ldg(b1v + col), by = __ldg(b1v + col + 1);
                float t0 = tanh_fast(acc[mt][nt][0] + bx);
                float t1 = tanh_fast(acc[mt][nt][1] + by);
                float t2 = tanh_fast(acc[mt][nt][2] + bx);
                float t3 = tanh_fast(acc[mt][nt][3] + by);
                *(uint32_t*)((char*)g_h + ((size_t)row0 * HID + col) * 2)
                    = pack_h2(t0, t1);
                *(uint32_t*)((char*)g_h + ((size_t)(row0 + 8) * HID + col) * 2)
                    = pack_h2(t2, t3);
            }
        }
    } else {
        const float dt = ts[step + 1] - ts[step];
        const float cn = cnext * dt;
        const float s6 = dt * (1.0f / 6.0f);

        #pragma unroll
        for (int mt = 0; mt < 4; mt++) {
            #pragma unroll
            for (int h = 0; h < 2; h++) {
                int row = m0 + wm * 64 + mt * 16 + r + 8 * h;   // = b*NTRAJ + n
                #pragma unroll
                for (int nt = 0; nt < 4; nt++) {
                    int col = n0 + wn * 32 + nt * 8 + 2 * cq;
                    float v0 = acc[mt][nt][2 * h + 0];
                    float v1 = acc[mt][nt][2 * h + 1];
                    size_t idx = (size_t)row * LAT + col;
                    if (mode == 0) {
                        g_ksum[idx] = v0;  g_ksum[idx + 1] = v1;
                        float xi0 = fmaf(cn, v0, g_x[idx]);
                        float xi1 = fmaf(cn, v1, g_x[idx + 1]);
                        *(uint32_t*)((char*)g_xin + idx * 2) = pack_h2(xi0, xi1);
                    } else if (mode == 1) {
                        g_ksum[idx]     += 2.f * v0;
                        g_ksum[idx + 1] += 2.f * v1;
                        float xi0 = fmaf(cn, v0, g_x[idx]);
                        float xi1 = fmaf(cn, v1, g_x[idx + 1]);
                        *(uint32_t*)((char*)g_xin + idx * 2) = pack_h2(xi0, xi1);
                    } else {
                        float x0 = g_x[idx] + s6 * (g_ksum[idx] + v0);
                        float x1 = g_x[idx + 1] + s6 * (g_ksum[idx + 1] + v1);
                        g_x[idx] = x0;   g_x[idx + 1] = x1;
                        *(uint32_t*)((char*)g_xin + idx * 2) = pack_h2(x0, x1);
                        size_t o = ((size_t)row * TSTEPS + (step + 1)) * LAT + col;
                        out[o] = x0; out[o + 1] = x1;
                    }
                }
            }
        }
    }
}

// ---------------- launch ------------------------------------------------------
extern "C" void kernel_launch(void* const* d_in, const int* in_sizes, int n_in,
                              void* d_out, int out_size) {
    const float* fp = (const float*)d_in[0];
    const float* ts = (const float*)d_in[1];
    const float* W1 = (const float*)d_in[2];
    const float* b1 = (const float*)d_in[3];
    const float* W2 = (const float*)d_in[4];
    float* out = (float*)d_out;

    static int attr_done = 0;
    if (!attr_done) {
        cudaFuncSetAttribute(k_mm<LAT, true>,
                             cudaFuncAttributeMaxDynamicSharedMemorySize, SMEM_TOT);
        cudaFuncSetAttribute(k_mm<HID, false>,
                             cudaFuncAttributeMaxDynamicSharedMemorySize, SMEM_TOT);
        attr_done = 1;
    }

    k_init<<<(MTOT * LAT + 255) / 256, 256>>>(fp, out);
    k_w1t<<<(LAT * HID + 255) / 256, 256>>>(W1);
    k_w2t<<<(HID * LAT + 255) / 256, 256>>>(W2);

    dim3 g1(HID / 128, MTOT / 128);   // (8, 128) = 1024 blocks
    dim3 g2(LAT / 128, MTOT / 128);   // (2, 128) = 256 blocks

    for (int s = 0; s < TSTEPS - 1; s++) {
        // eval 1 -> k1: ksum = k1,  xin = x + 0.5*dt*k1
        k_mm<LAT,  true ><<<g1, 256, SMEM_TOT>>>(b1, ts, s, 0, 0.0f, nullptr);
        k_mm<HID,  false><<<g2, 256, SMEM_TOT>>>(nullptr, ts, s, 0, 0.5f, out);
        // eval 2 -> k2: ksum += 2*k2, xin = x + 0.5*dt*k2
        k_mm<LAT,  true ><<<g1, 256, SMEM_TOT>>>(b1, ts, s, 0, 0.0f, nullptr);
        k_mm<HID,  false><<<g2, 256, SMEM_TOT>>>(nullptr, ts, s, 1, 0.5f, out);
        // eval 3 -> k3: ksum += 2*k3, xin = x + dt*k3
        k_mm<LAT,  true ><<<g1, 256, SMEM_TOT>>>(b1, ts, s, 0, 0.0f, nullptr);
        k_mm<HID,  false><<<g2, 256, SMEM_TOT>>>(nullptr, ts, s, 1, 1.0f, out);
        // eval 4 -> k4: x += dt/6*(ksum + k4); write slice; xin = x_new
        k_mm<LAT,  true ><<<g1, 256, SMEM_TOT>>>(b1, ts, s, 0, 0.0f, nullptr);
        k_mm<HID,  false><<<g2, 256, SMEM_TOT>>>(nullptr, ts, s, 2, 0.0f, out);
    }
}